// round 11
// baseline (speedup 1.0000x reference)
#include <cuda_runtime.h>
#include <cuda_fp16.h>
#include <cstdint>

// ---------------- Problem constants ----------------
#define NN 50000
#define EE 800000
#define KIN 256
#define HD 4
#define DD 64
#define OUTF (HD*DD)   // 256
#define SCAN_NB ((NN + 1023) / 1024)   // 49

// ---------------- Scratch (device globals; referenced ONLY from device code) ----------------
__device__ float  g_hp[(size_t)NN * OUTF];     // fp32 projected features (node_dots)
__device__ __half g_hph[(size_t)NN * OUTF];    // fp16 copy (aggregation gather)
__device__ float  g_wt[KIN * OUTF];            // W^T pre-rounded to tf32 (RNA)
__device__ float4 g_ssrc[NN];
__device__ float4 g_sdst[NN];
__device__ int    g_deg[NN];
__device__ int    g_off[NN];
__device__ int    g_cursor[NN];
__device__ int    g_csr[EE];
__device__ int    g_bsum[SCAN_NB];
__device__ int    g_boff[SCAN_NB];
__device__ int    g_stride;

// ---------------- detect int64 vs int32 edge_index ----------------
__global__ void detect_kernel(const int* __restrict__ ei) {
    if (blockIdx.x == 0 && threadIdx.x == 0) {
        int odd_nz = 0, even_nz = 0;
        for (int i = 0; i < 512; i++) {
            if (ei[2 * i + 1] != 0) odd_nz++;
            if (ei[2 * i] != 0)     even_nz++;
        }
        g_stride = (odd_nz == 0 && even_nz > 0) ? 2 : 1;
    }
}

// ---------------- zero degree ----------------
__global__ void zero_deg_kernel() {
    int i = blockIdx.x * blockDim.x + threadIdx.x;
    if (i < NN) g_deg[i] = 0;
}

__device__ __forceinline__ float tf32r(float f) {
    uint32_t u;
    asm("cvt.rna.tf32.f32 %0, %1;" : "=r"(u) : "f"(f));
    return __uint_as_float(u);
}

// ---------------- transpose W (+ tf32 pre-round) ----------------
__global__ void transpose_w_kernel(const float* __restrict__ W) {
    __shared__ float tile[32][33];
    int bx = blockIdx.x * 32, by = blockIdx.y * 32;
    int tx = threadIdx.x, ty = threadIdx.y;
    #pragma unroll
    for (int r = 0; r < 4; r++)
        tile[ty + r * 8][tx] = W[(size_t)(by + ty + r * 8) * OUTF + bx + tx];
    __syncthreads();
    #pragma unroll
    for (int r = 0; r < 4; r++)
        g_wt[(size_t)(bx + ty + r * 8) * KIN + by + tx] = tf32r(tile[tx][ty + r * 8]);
}

// ---------------- tf32 GEMM: cp.async 2-stage pipeline, no cvt in kernel ----------------
#define GBM 128
#define GBN 128
#define GBK 32
#define LDK 36   // (row*36+col)%32 = (row*4+col)%32 -> conflict-free fragments

__device__ __forceinline__ void mma_tf32(float4& d,
                                         uint32_t a0, uint32_t a1, uint32_t a2, uint32_t a3,
                                         uint32_t b0, uint32_t b1) {
    asm volatile(
        "mma.sync.aligned.m16n8k8.row.col.f32.tf32.tf32.f32 "
        "{%0,%1,%2,%3}, {%4,%5,%6,%7}, {%8,%9}, {%0,%1,%2,%3};"
        : "+f"(d.x), "+f"(d.y), "+f"(d.z), "+f"(d.w)
        : "r"(a0), "r"(a1), "r"(a2), "r"(a3), "r"(b0), "r"(b1));
}

__global__ __launch_bounds__(256, 2)
void tf32_gemm_kernel(const float* __restrict__ A, int M) {
    __shared__ uint32_t As[2][GBM * LDK];
    __shared__ uint32_t Bs[2][GBN * LDK];
    int tid  = threadIdx.x;
    int warp = tid >> 5, lane = tid & 31;
    int wm = warp & 1, wn = warp >> 1;          // 2x4 warps; warp tile 64x32
    int rowBase = blockIdx.y * GBM;
    int colBase = blockIdx.x * GBN;

    float4 acc[4][4];
    #pragma unroll
    for (int i = 0; i < 4; i++)
        #pragma unroll
        for (int j = 0; j < 4; j++) acc[i][j] = make_float4(0.f, 0.f, 0.f, 0.f);

    int la_row = tid >> 3;          // 0..31
    int la_col = (tid & 7) * 4;     // 0,4,..,28

    // async stage loader: A rows (zero-filled OOB) + B rows
    auto load_stage = [&](int st, int k0) {
        #pragma unroll
        for (int r = 0; r < 4; r++) {
            int row = la_row + r * 32;
            int gr = rowBase + row;
            const float* srca = A + (size_t)(gr < M ? gr : M - 1) * KIN + k0 + la_col;
            int zf = (gr < M) ? 16 : 0;
            uint32_t da = (uint32_t)__cvta_generic_to_shared(&As[st][row * LDK + la_col]);
            asm volatile("cp.async.cg.shared.global [%0], [%1], 16, %2;\n"
                         :: "r"(da), "l"(srca), "r"(zf) : "memory");
            int gn = colBase + row;     // < 256 always
            const float* srcb = g_wt + (size_t)gn * KIN + k0 + la_col;
            uint32_t db = (uint32_t)__cvta_generic_to_shared(&Bs[st][row * LDK + la_col]);
            asm volatile("cp.async.cg.shared.global [%0], [%1], 16, 16;\n"
                         :: "r"(db), "l"(srcb) : "memory");
        }
        asm volatile("cp.async.commit_group;\n" ::: "memory");
    };

    load_stage(0, 0);

    const int NIT = KIN / GBK;      // 8
    int g4 = lane >> 2, l4 = lane & 3;
    for (int i = 0; i < NIT; i++) {
        if (i + 1 < NIT) {
            load_stage((i + 1) & 1, (i + 1) * GBK);
            asm volatile("cp.async.wait_group 1;\n" ::: "memory");
        } else {
            asm volatile("cp.async.wait_group 0;\n" ::: "memory");
        }
        __syncthreads();
        const uint32_t* Ab = As[i & 1];
        const uint32_t* Bb = Bs[i & 1];
        #pragma unroll
        for (int ks = 0; ks < 4; ks++) {
            int kb = ks * 8;
            uint32_t af[4][4], bf[4][2];
            #pragma unroll
            for (int mt = 0; mt < 4; mt++) {
                int r0 = wm * 64 + mt * 16 + g4;
                af[mt][0] = Ab[ r0      * LDK + kb + l4    ];
                af[mt][1] = Ab[(r0 + 8) * LDK + kb + l4    ];
                af[mt][2] = Ab[ r0      * LDK + kb + l4 + 4];
                af[mt][3] = Ab[(r0 + 8) * LDK + kb + l4 + 4];
            }
            #pragma unroll
            for (int nt = 0; nt < 4; nt++) {
                int n0 = wn * 32 + nt * 8 + g4;
                bf[nt][0] = Bb[n0 * LDK + kb + l4    ];
                bf[nt][1] = Bb[n0 * LDK + kb + l4 + 4];
            }
            #pragma unroll
            for (int mt = 0; mt < 4; mt++)
                #pragma unroll
                for (int nt = 0; nt < 4; nt++)
                    mma_tf32(acc[mt][nt], af[mt][0], af[mt][1], af[mt][2], af[mt][3],
                             bf[nt][0], bf[nt][1]);
        }
        __syncthreads();
    }

    #pragma unroll
    for (int mt = 0; mt < 4; mt++) {
        int r = rowBase + wm * 64 + mt * 16 + g4;
        #pragma unroll
        for (int nt = 0; nt < 4; nt++) {
            int c = colBase + wn * 32 + nt * 8 + l4 * 2;
            if (r < M) {
                *reinterpret_cast<float2*>(g_hp + (size_t)r * OUTF + c) =
                    make_float2(acc[mt][nt].x, acc[mt][nt].y);
                *reinterpret_cast<__half2*>(g_hph + (size_t)r * OUTF + c) =
                    __floats2half2_rn(acc[mt][nt].x, acc[mt][nt].y);
            }
            if (r + 8 < M) {
                *reinterpret_cast<float2*>(g_hp + (size_t)(r + 8) * OUTF + c) =
                    make_float2(acc[mt][nt].z, acc[mt][nt].w);
                *reinterpret_cast<__half2*>(g_hph + (size_t)(r + 8) * OUTF + c) =
                    __floats2half2_rn(acc[mt][nt].z, acc[mt][nt].w);
            }
        }
    }
}

// ---------------- per-node logits ----------------
__global__ void node_dots_kernel(const float* __restrict__ a_src,
                                 const float* __restrict__ a_dst) {
    int warp = (blockIdx.x * blockDim.x + threadIdx.x) >> 5;
    int lane = threadIdx.x & 31;
    if (warp >= NN) return;
    const float4* row = reinterpret_cast<const float4*>(g_hp + (size_t)warp * OUTF);
    const float4* as4 = reinterpret_cast<const float4*>(a_src);
    const float4* ad4 = reinterpret_cast<const float4*>(a_dst);
    float4 r0 = row[lane * 2], r1 = row[lane * 2 + 1];
    float4 a0 = as4[lane * 2], a1 = as4[lane * 2 + 1];
    float4 d0 = ad4[lane * 2], d1 = ad4[lane * 2 + 1];
    float ps = r0.x*a0.x + r0.y*a0.y + r0.z*a0.z + r0.w*a0.w
             + r1.x*a1.x + r1.y*a1.y + r1.z*a1.z + r1.w*a1.w;
    float pd = r0.x*d0.x + r0.y*d0.y + r0.z*d0.z + r0.w*d0.w
             + r1.x*d1.x + r1.y*d1.y + r1.z*d1.z + r1.w*d1.w;
    #pragma unroll
    for (int o = 4; o; o >>= 1) {
        ps += __shfl_xor_sync(0xffffffffu, ps, o);
        pd += __shfl_xor_sync(0xffffffffu, pd, o);
    }
    float s0 = __shfl_sync(0xffffffffu, ps, 0),  s1 = __shfl_sync(0xffffffffu, ps, 8);
    float s2 = __shfl_sync(0xffffffffu, ps, 16), s3 = __shfl_sync(0xffffffffu, ps, 24);
    float d0s = __shfl_sync(0xffffffffu, pd, 0),  d1s = __shfl_sync(0xffffffffu, pd, 8);
    float d2s = __shfl_sync(0xffffffffu, pd, 16), d3s = __shfl_sync(0xffffffffu, pd, 24);
    if (lane == 0) {
        g_ssrc[warp] = make_float4(s0, s1, s2, s3);
        g_sdst[warp] = make_float4(d0s, d1s, d2s, d3s);
    }
}

// ---------------- count in-degree ----------------
__global__ void count_deg_kernel(const int* __restrict__ ei, const int* __restrict__ dst_sep) {
    int e = blockIdx.x * blockDim.x + threadIdx.x;
    if (e >= EE) return;
    int st = g_stride;
    const int* d_base = dst_sep ? dst_sep : ei + (size_t)EE * st;
    int u = d_base[(size_t)e * st];
    if (u >= 0 && u < NN) atomicAdd(&g_deg[u], 1);
}

// ---------------- multi-block exclusive scan ----------------
__global__ void scan_part1_kernel() {
    __shared__ int warpsums[32];
    int t = threadIdx.x, lane = t & 31, wid = t >> 5;
    int idx = blockIdx.x * 1024 + t;
    int v = (idx < NN) ? g_deg[idx] : 0;
    int x = v;
    #pragma unroll
    for (int o = 1; o < 32; o <<= 1) {
        int y = __shfl_up_sync(0xffffffffu, x, o);
        if (lane >= o) x += y;
    }
    if (lane == 31) warpsums[wid] = x;
    __syncthreads();
    if (wid == 0) {
        int s = warpsums[lane];
        #pragma unroll
        for (int o = 1; o < 32; o <<= 1) {
            int y = __shfl_up_sync(0xffffffffu, s, o);
            if (lane >= o) s += y;
        }
        warpsums[lane] = s;
    }
    __syncthreads();
    int incl = x + (wid > 0 ? warpsums[wid - 1] : 0);
    if (idx < NN) g_off[idx] = incl - v;
    if (t == 1023) g_bsum[blockIdx.x] = incl;
}

__global__ void scan_part2_kernel() {
    __shared__ int ws[2];
    int t = threadIdx.x, lane = t & 31, wid = t >> 5;
    int v = (t < SCAN_NB) ? g_bsum[t] : 0;
    int x = v;
    #pragma unroll
    for (int o = 1; o < 32; o <<= 1) {
        int y = __shfl_up_sync(0xffffffffu, x, o);
        if (lane >= o) x += y;
    }
    if (lane == 31) ws[wid] = x;
    __syncthreads();
    int excl = x - v + (wid > 0 ? ws[0] : 0);
    if (t < SCAN_NB) g_boff[t] = excl;
}

__global__ void scan_part3_kernel() {
    int idx = blockIdx.x * blockDim.x + threadIdx.x;
    if (idx < NN) {
        int o = g_off[idx] + g_boff[idx >> 10];
        g_off[idx] = o;
        g_cursor[idx] = o;
    }
}

// ---------------- pure CSR scatter ----------------
__global__ void scatter_kernel(const int* __restrict__ ei, const int* __restrict__ dst_sep) {
    int e = blockIdx.x * blockDim.x + threadIdx.x;
    if (e >= EE) return;
    int st = g_stride;
    const int* d_base = dst_sep ? dst_sep : ei + (size_t)EE * st;
    int ud = d_base[(size_t)e * st];
    if (ud < 0 || ud >= NN) return;
    int us = ei[(size_t)e * st];
    if (us < 0) us = 0;
    if (us >= NN) us = NN - 1;
    int p = atomicAdd(&g_cursor[ud], 1);
    if (p >= 0 && p < EE) g_csr[p] = us;
}

// ---------------- fused softmax + aggregation: warp/node, fp16 gather, tile prefetch ----------------
__global__ __launch_bounds__(256)
void aggregate_fused_kernel(float* __restrict__ out) {
    int lane = threadIdx.x;
    int yn = threadIdx.y;
    int node = blockIdx.x * 8 + yn;
    if (node >= NN) return;
    int start = g_off[node], dn = g_deg[node];
    int hq = lane >> 3;                  // my head
    int pe = lane & 7;                   // producer edge slot
    float sdv = (&g_sdst[node].x)[hq];

    float accf[8] = {0.f,0.f,0.f,0.f,0.f,0.f,0.f,0.f};
    float z = 0.f;

    int tiles = (dn + 7) >> 3;
    int s_cur = 0; float w_cur = 0.f;
    if (tiles > 0) {
        int cnt0 = min(8, dn);
        if (pe < cnt0) {
            s_cur = g_csr[start + pe];
            float x = (&g_ssrc[s_cur].x)[hq] + sdv;
            x = fmaxf(x, 0.2f * x);
            w_cur = __expf(x);
        }
    }

    for (int t = 0; t < tiles; t++) {
        int base = t * 8;
        int cnt = min(8, dn - base);
        // prefetch next tile's CSR entry early (hide L2 latency under consume)
        int nbase = base + 8;
        int ncnt = (nbase < dn) ? min(8, dn - nbase) : 0;
        int s_next = 0;
        if (pe < ncnt) s_next = g_csr[start + nbase + pe];

        #pragma unroll
        for (int e = 0; e < 8; e++) {
            if (e >= cnt) break;                       // cnt uniform per warp
            int   se = __shfl_sync(0xffffffffu, s_cur, e);
            float we = __shfl_sync(0xffffffffu, w_cur, (hq << 3) | e);
            uint4 vu = *reinterpret_cast<const uint4*>(g_hph + (size_t)se * OUTF + lane * 8);
            const __half2* vh = reinterpret_cast<const __half2*>(&vu);
            z += we;
            #pragma unroll
            for (int q = 0; q < 4; q++) {
                float2 f = __half22float2(vh[q]);
                accf[q * 2]     += we * f.x;
                accf[q * 2 + 1] += we * f.y;
            }
        }
        // produce next tile's weight (s_next load has had time to land)
        float w_next = 0.f;
        if (pe < ncnt) {
            float x = (&g_ssrc[s_next].x)[hq] + sdv;
            x = fmaxf(x, 0.2f * x);
            w_next = __expf(x);
        }
        s_cur = s_next; w_cur = w_next;
    }
    float inv = 1.f / (z + 1e-16f);
    float4 o0 = make_float4(accf[0]*inv, accf[1]*inv, accf[2]*inv, accf[3]*inv);
    float4 o1 = make_float4(accf[4]*inv, accf[5]*inv, accf[6]*inv, accf[7]*inv);
    *reinterpret_cast<float4*>(out + (size_t)node * OUTF + lane * 8)     = o0;
    *reinterpret_cast<float4*>(out + (size_t)node * OUTF + lane * 8 + 4) = o1;
}

// ---------------- launch ----------------
extern "C" void kernel_launch(void* const* d_in, const int* in_sizes, int n_in,
                              void* d_out, int out_size) {
    const float* h     = nullptr;
    const int*   ei    = nullptr;
    const int*   src2  = nullptr;
    const int*   dst2  = nullptr;
    const float* W     = nullptr;
    const float* a_src = nullptr;
    const float* a_dst = nullptr;

    for (int i = 0; i < n_in; i++) {
        long sz = in_sizes[i];
        if (sz == 12800000L)      h = (const float*)d_in[i];
        else if (sz == 65536L)    W = (const float*)d_in[i];
        else if (sz == 256L) {
            if (!a_src) a_src = (const float*)d_in[i];
            else        a_dst = (const float*)d_in[i];
        }
        else if (sz == 1600000L)  ei = (const int*)d_in[i];
        else if (sz == 800000L) {
            if (!src2) src2 = (const int*)d_in[i];
            else       dst2 = (const int*)d_in[i];
        }
    }
    if (!h)                       h     = (const float*)d_in[0];
    if (!ei && !src2 && n_in > 1) ei    = (const int*)d_in[1];
    if (!W && n_in > 2)           W     = (const float*)d_in[2];
    if (!a_src && n_in > 3)       a_src = (const float*)d_in[3];
    if (!a_dst && n_in > 4)       a_dst = (const float*)d_in[4];

    const int* ebase = ei ? ei : src2;
    const int* dsep  = ei ? nullptr : dst2;
    float* out = (float*)d_out;

    cudaStream_t s2 = 0;
    cudaEvent_t ev_fork = nullptr, ev_join = nullptr;
    bool forked = (cudaStreamCreateWithFlags(&s2, cudaStreamNonBlocking) == cudaSuccess) &&
                  (cudaEventCreateWithFlags(&ev_fork, cudaEventDisableTiming) == cudaSuccess) &&
                  (cudaEventCreateWithFlags(&ev_join, cudaEventDisableTiming) == cudaSuccess);

    detect_kernel<<<1, 32>>>(ebase);

    if (forked) {
        cudaEventRecord(ev_fork, 0);
        cudaStreamWaitEvent(s2, ev_fork, 0);
    }
    cudaStream_t sb = forked ? s2 : 0;

    // CSR chain on side stream
    zero_deg_kernel<<<(NN + 255) / 256, 256, 0, sb>>>();
    count_deg_kernel<<<(EE + 255) / 256, 256, 0, sb>>>(ebase, dsep);
    scan_part1_kernel<<<SCAN_NB, 1024, 0, sb>>>();
    scan_part2_kernel<<<1, 64, 0, sb>>>();
    scan_part3_kernel<<<(NN + 255) / 256, 256, 0, sb>>>();
    scatter_kernel<<<(EE + 255) / 256, 256, 0, sb>>>(ebase, dsep);

    // GEMM chain on main stream
    dim3 tblock(32, 8);
    transpose_w_kernel<<<dim3(8, 8), tblock>>>(W);
    dim3 ggrid(OUTF / GBN, (NN + GBM - 1) / GBM);
    tf32_gemm_kernel<<<ggrid, 256>>>(h, NN);
    node_dots_kernel<<<(NN * 32 + 255) / 256, 256>>>(a_src, a_dst);

    if (forked) {
        cudaEventRecord(ev_join, s2);
        cudaStreamWaitEvent(0, ev_join, 0);
    }

    dim3 ablock(32, 8);
    aggregate_fused_kernel<<<(NN + 7) / 8, ablock>>>(out);
}

// round 12
// speedup vs baseline: 1.2083x; 1.2083x over previous
#include <cuda_runtime.h>
#include <cuda_fp16.h>
#include <cstdint>

// ---------------- Problem constants ----------------
#define NN 50000
#define EE 800000
#define KIN 256
#define HD 4
#define DD 64
#define OUTF (HD*DD)   // 256
#define SCAN_NB ((NN + 1023) / 1024)   // 49

// ---------------- Scratch (device globals; referenced ONLY from device code) ----------------
__device__ float  g_hp[(size_t)NN * OUTF];     // fp32 projected features (node_dots)
__device__ __half g_hph[(size_t)NN * OUTF];    // fp16 copy (aggregation gather)
__device__ float  g_wt[KIN * OUTF];            // W^T pre-rounded to tf32
__device__ float4 g_ssrc[NN];
__device__ float4 g_sdst[NN];
__device__ int    g_deg[NN];
__device__ int    g_off[NN];
__device__ int    g_cursor[NN];
__device__ int    g_csr[EE];
__device__ int    g_bsum[SCAN_NB];
__device__ int    g_boff[SCAN_NB];
__device__ int    g_stride;

// ---------------- detect int64 vs int32 edge_index (warp-parallel) ----------------
__global__ void detect_kernel(const int* __restrict__ ei) {
    int lane = threadIdx.x & 31;
    int odd_nz = 0, even_nz = 0;
    for (int i = lane; i < 512; i += 32) {
        if (ei[2 * i + 1] != 0) odd_nz++;
        if (ei[2 * i] != 0)     even_nz++;
    }
    unsigned ob = __ballot_sync(0xffffffffu, odd_nz > 0);
    unsigned eb = __ballot_sync(0xffffffffu, even_nz > 0);
    if (lane == 0) g_stride = (ob == 0u && eb != 0u) ? 2 : 1;
}

// ---------------- zero degree ----------------
__global__ void zero_deg_kernel() {
    int i = blockIdx.x * blockDim.x + threadIdx.x;
    if (i < NN) g_deg[i] = 0;
}

__device__ __forceinline__ float tf32r(float f) {
    uint32_t u;
    asm("cvt.rna.tf32.f32 %0, %1;" : "=r"(u) : "f"(f));
    return __uint_as_float(u);
}

// ---------------- transpose W (+ tf32 pre-round) ----------------
__global__ void transpose_w_kernel(const float* __restrict__ W) {
    __shared__ float tile[32][33];
    int bx = blockIdx.x * 32, by = blockIdx.y * 32;
    int tx = threadIdx.x, ty = threadIdx.y;
    #pragma unroll
    for (int r = 0; r < 4; r++)
        tile[ty + r * 8][tx] = W[(size_t)(by + ty + r * 8) * OUTF + bx + tx];
    __syncthreads();
    #pragma unroll
    for (int r = 0; r < 4; r++)
        g_wt[(size_t)(bx + ty + r * 8) * KIN + by + tx] = tf32r(tile[tx][ty + r * 8]);
}

// ---------------- tf32 tensor-core GEMM (R10 version: cvt at smem store) ----------------
#define GBM 128
#define GBN 128
#define GBK 32
#define LDK 36

__device__ __forceinline__ void mma_tf32(float4& d,
                                         uint32_t a0, uint32_t a1, uint32_t a2, uint32_t a3,
                                         uint32_t b0, uint32_t b1) {
    asm volatile(
        "mma.sync.aligned.m16n8k8.row.col.f32.tf32.tf32.f32 "
        "{%0,%1,%2,%3}, {%4,%5,%6,%7}, {%8,%9}, {%0,%1,%2,%3};"
        : "+f"(d.x), "+f"(d.y), "+f"(d.z), "+f"(d.w)
        : "r"(a0), "r"(a1), "r"(a2), "r"(a3), "r"(b0), "r"(b1));
}

__global__ __launch_bounds__(256, 2)
void tf32_gemm_kernel(const float* __restrict__ A, int M) {
    __shared__ uint32_t As[GBM * LDK];
    __shared__ uint32_t Bs[GBN * LDK];
    int tid  = threadIdx.x;
    int warp = tid >> 5, lane = tid & 31;
    int wm = warp & 1, wn = warp >> 1;
    int rowBase = blockIdx.y * GBM;
    int colBase = blockIdx.x * GBN;

    float4 acc[4][4];
    #pragma unroll
    for (int i = 0; i < 4; i++)
        #pragma unroll
        for (int j = 0; j < 4; j++) acc[i][j] = make_float4(0.f, 0.f, 0.f, 0.f);

    int la_row = tid >> 3;
    int la_col = (tid & 7) * 4;

    float4 pa[4], pb[4];
    #pragma unroll
    for (int r = 0; r < 4; r++) {
        int gr = rowBase + la_row + r * 32;
        pa[r] = (gr < M) ? *reinterpret_cast<const float4*>(A + (size_t)gr * KIN + la_col)
                         : make_float4(0.f, 0.f, 0.f, 0.f);
        int gn = colBase + la_row + r * 32;
        pb[r] = *reinterpret_cast<const float4*>(g_wt + (size_t)gn * KIN + la_col);
    }

    for (int k0 = 0; k0 < KIN; k0 += GBK) {
        #pragma unroll
        for (int r = 0; r < 4; r++) {
            uint4 av;
            av.x = __float_as_uint(tf32r(pa[r].x));
            av.y = __float_as_uint(tf32r(pa[r].y));
            av.z = __float_as_uint(tf32r(pa[r].z));
            av.w = __float_as_uint(tf32r(pa[r].w));
            *reinterpret_cast<uint4*>(&As[(la_row + r * 32) * LDK + la_col]) = av;
            *reinterpret_cast<uint4*>(&Bs[(la_row + r * 32) * LDK + la_col]) =
                *reinterpret_cast<uint4*>(&pb[r]);
        }
        __syncthreads();
        if (k0 + GBK < KIN) {
            #pragma unroll
            for (int r = 0; r < 4; r++) {
                int gr = rowBase + la_row + r * 32;
                pa[r] = (gr < M) ? *reinterpret_cast<const float4*>(A + (size_t)gr * KIN + k0 + GBK + la_col)
                                 : make_float4(0.f, 0.f, 0.f, 0.f);
                int gn = colBase + la_row + r * 32;
                pb[r] = *reinterpret_cast<const float4*>(g_wt + (size_t)gn * KIN + k0 + GBK + la_col);
            }
        }
        int g4 = lane >> 2, l4 = lane & 3;
        #pragma unroll
        for (int ks = 0; ks < 4; ks++) {
            int kb = ks * 8;
            uint32_t af[4][4], bf[4][2];
            #pragma unroll
            for (int mt = 0; mt < 4; mt++) {
                int r0 = wm * 64 + mt * 16 + g4;
                af[mt][0] = As[ r0      * LDK + kb + l4    ];
                af[mt][1] = As[(r0 + 8) * LDK + kb + l4    ];
                af[mt][2] = As[ r0      * LDK + kb + l4 + 4];
                af[mt][3] = As[(r0 + 8) * LDK + kb + l4 + 4];
            }
            #pragma unroll
            for (int nt = 0; nt < 4; nt++) {
                int n0 = wn * 32 + nt * 8 + g4;
                bf[nt][0] = Bs[n0 * LDK + kb + l4    ];
                bf[nt][1] = Bs[n0 * LDK + kb + l4 + 4];
            }
            #pragma unroll
            for (int mt = 0; mt < 4; mt++)
                #pragma unroll
                for (int nt = 0; nt < 4; nt++)
                    mma_tf32(acc[mt][nt], af[mt][0], af[mt][1], af[mt][2], af[mt][3],
                             bf[nt][0], bf[nt][1]);
        }
        __syncthreads();
    }

    int g4 = lane >> 2, l4 = lane & 3;
    #pragma unroll
    for (int mt = 0; mt < 4; mt++) {
        int r = rowBase + wm * 64 + mt * 16 + g4;
        #pragma unroll
        for (int nt = 0; nt < 4; nt++) {
            int c = colBase + wn * 32 + nt * 8 + l4 * 2;
            if (r < M) {
                *reinterpret_cast<float2*>(g_hp + (size_t)r * OUTF + c) =
                    make_float2(acc[mt][nt].x, acc[mt][nt].y);
                *reinterpret_cast<__half2*>(g_hph + (size_t)r * OUTF + c) =
                    __floats2half2_rn(acc[mt][nt].x, acc[mt][nt].y);
            }
            if (r + 8 < M) {
                *reinterpret_cast<float2*>(g_hp + (size_t)(r + 8) * OUTF + c) =
                    make_float2(acc[mt][nt].z, acc[mt][nt].w);
                *reinterpret_cast<__half2*>(g_hph + (size_t)(r + 8) * OUTF + c) =
                    __floats2half2_rn(acc[mt][nt].z, acc[mt][nt].w);
            }
        }
    }
}

// ---------------- per-node logits ----------------
__global__ void node_dots_kernel(const float* __restrict__ a_src,
                                 const float* __restrict__ a_dst) {
    int warp = (blockIdx.x * blockDim.x + threadIdx.x) >> 5;
    int lane = threadIdx.x & 31;
    if (warp >= NN) return;
    const float4* row = reinterpret_cast<const float4*>(g_hp + (size_t)warp * OUTF);
    const float4* as4 = reinterpret_cast<const float4*>(a_src);
    const float4* ad4 = reinterpret_cast<const float4*>(a_dst);
    float4 r0 = row[lane * 2], r1 = row[lane * 2 + 1];
    float4 a0 = as4[lane * 2], a1 = as4[lane * 2 + 1];
    float4 d0 = ad4[lane * 2], d1 = ad4[lane * 2 + 1];
    float ps = r0.x*a0.x + r0.y*a0.y + r0.z*a0.z + r0.w*a0.w
             + r1.x*a1.x + r1.y*a1.y + r1.z*a1.z + r1.w*a1.w;
    float pd = r0.x*d0.x + r0.y*d0.y + r0.z*d0.z + r0.w*d0.w
             + r1.x*d1.x + r1.y*d1.y + r1.z*d1.z + r1.w*d1.w;
    #pragma unroll
    for (int o = 4; o; o >>= 1) {
        ps += __shfl_xor_sync(0xffffffffu, ps, o);
        pd += __shfl_xor_sync(0xffffffffu, pd, o);
    }
    float s0 = __shfl_sync(0xffffffffu, ps, 0),  s1 = __shfl_sync(0xffffffffu, ps, 8);
    float s2 = __shfl_sync(0xffffffffu, ps, 16), s3 = __shfl_sync(0xffffffffu, ps, 24);
    float d0s = __shfl_sync(0xffffffffu, pd, 0),  d1s = __shfl_sync(0xffffffffu, pd, 8);
    float d2s = __shfl_sync(0xffffffffu, pd, 16), d3s = __shfl_sync(0xffffffffu, pd, 24);
    if (lane == 0) {
        g_ssrc[warp] = make_float4(s0, s1, s2, s3);
        g_sdst[warp] = make_float4(d0s, d1s, d2s, d3s);
    }
}

// ---------------- count in-degree ----------------
__global__ void count_deg_kernel(const int* __restrict__ ei, const int* __restrict__ dst_sep) {
    int e = blockIdx.x * blockDim.x + threadIdx.x;
    if (e >= EE) return;
    int st = g_stride;
    const int* d_base = dst_sep ? dst_sep : ei + (size_t)EE * st;
    int u = d_base[(size_t)e * st];
    if (u >= 0 && u < NN) atomicAdd(&g_deg[u], 1);
}

// ---------------- multi-block exclusive scan ----------------
__global__ void scan_part1_kernel() {
    __shared__ int warpsums[32];
    int t = threadIdx.x, lane = t & 31, wid = t >> 5;
    int idx = blockIdx.x * 1024 + t;
    int v = (idx < NN) ? g_deg[idx] : 0;
    int x = v;
    #pragma unroll
    for (int o = 1; o < 32; o <<= 1) {
        int y = __shfl_up_sync(0xffffffffu, x, o);
        if (lane >= o) x += y;
    }
    if (lane == 31) warpsums[wid] = x;
    __syncthreads();
    if (wid == 0) {
        int s = warpsums[lane];
        #pragma unroll
        for (int o = 1; o < 32; o <<= 1) {
            int y = __shfl_up_sync(0xffffffffu, s, o);
            if (lane >= o) s += y;
        }
        warpsums[lane] = s;
    }
    __syncthreads();
    int incl = x + (wid > 0 ? warpsums[wid - 1] : 0);
    if (idx < NN) g_off[idx] = incl - v;
    if (t == 1023) g_bsum[blockIdx.x] = incl;
}

__global__ void scan_part2_kernel() {
    __shared__ int ws[2];
    int t = threadIdx.x, lane = t & 31, wid = t >> 5;
    int v = (t < SCAN_NB) ? g_bsum[t] : 0;
    int x = v;
    #pragma unroll
    for (int o = 1; o < 32; o <<= 1) {
        int y = __shfl_up_sync(0xffffffffu, x, o);
        if (lane >= o) x += y;
    }
    if (lane == 31) ws[wid] = x;
    __syncthreads();
    int excl = x - v + (wid > 0 ? ws[0] : 0);
    if (t < SCAN_NB) g_boff[t] = excl;
}

__global__ void scan_part3_kernel() {
    int idx = blockIdx.x * blockDim.x + threadIdx.x;
    if (idx < NN) {
        int o = g_off[idx] + g_boff[idx >> 10];
        g_off[idx] = o;
        g_cursor[idx] = o;
    }
}

// ---------------- pure CSR scatter ----------------
__global__ void scatter_kernel(const int* __restrict__ ei, const int* __restrict__ dst_sep) {
    int e = blockIdx.x * blockDim.x + threadIdx.x;
    if (e >= EE) return;
    int st = g_stride;
    const int* d_base = dst_sep ? dst_sep : ei + (size_t)EE * st;
    int ud = d_base[(size_t)e * st];
    if (ud < 0 || ud >= NN) return;
    int us = ei[(size_t)e * st];
    if (us < 0) us = 0;
    if (us >= NN) us = NN - 1;
    int p = atomicAdd(&g_cursor[ud], 1);
    if (p >= 0 && p < EE) g_csr[p] = us;
}

// ---------------- fused softmax + aggregation: batched-load full tiles ----------------
// blockDim (32,8). Lane owns 8 halfs (16B) of the 256-wide row; head = lane>>3.
__global__ __launch_bounds__(256)
void aggregate_fused_kernel(float* __restrict__ out) {
    int lane = threadIdx.x;
    int yn = threadIdx.y;
    int node = blockIdx.x * 8 + yn;
    if (node >= NN) return;
    int start = g_off[node], dn = g_deg[node];
    int hq = lane >> 3;
    int pe = lane & 7;
    float sdv = (&g_sdst[node].x)[hq];

    float accf[8] = {0.f,0.f,0.f,0.f,0.f,0.f,0.f,0.f};
    float z = 0.f;

    int full = dn & ~7;           // multiple-of-8 edges
    // ---- full tiles: shfl-gather, then 8 batched independent loads (MLP=8) ----
    for (int base = 0; base < full; base += 8) {
        int s = g_csr[start + base + pe];
        float x = (&g_ssrc[s].x)[hq] + sdv;
        x = fmaxf(x, 0.2f * x);
        float w = __expf(x);

        int   se[8];
        float we[8];
        #pragma unroll
        for (int e = 0; e < 8; e++) {
            se[e] = __shfl_sync(0xffffffffu, s, e);
            we[e] = __shfl_sync(0xffffffffu, w, (hq << 3) | e);
        }
        uint4 vu[8];
        #pragma unroll
        for (int e = 0; e < 8; e++)
            vu[e] = *reinterpret_cast<const uint4*>(g_hph + (size_t)se[e] * OUTF + lane * 8);
        #pragma unroll
        for (int e = 0; e < 8; e++) {
            const __half2* vh = reinterpret_cast<const __half2*>(&vu[e]);
            z += we[e];
            #pragma unroll
            for (int q = 0; q < 4; q++) {
                float2 f = __half22float2(vh[q]);
                accf[q * 2]     += we[e] * f.x;
                accf[q * 2 + 1] += we[e] * f.y;
            }
        }
    }
    // ---- tail (< 8 edges) ----
    int cnt = dn - full;
    if (cnt > 0) {
        float w = 0.f; int s = 0;
        if (pe < cnt) {
            s = g_csr[start + full + pe];
            float x = (&g_ssrc[s].x)[hq] + sdv;
            x = fmaxf(x, 0.2f * x);
            w = __expf(x);
        }
        for (int e = 0; e < cnt; e++) {
            int   se = __shfl_sync(0xffffffffu, s, e);
            float we = __shfl_sync(0xffffffffu, w, (hq << 3) | e);
            uint4 vu = *reinterpret_cast<const uint4*>(g_hph + (size_t)se * OUTF + lane * 8);
            const __half2* vh = reinterpret_cast<const __half2*>(&vu);
            z += we;
            #pragma unroll
            for (int q = 0; q < 4; q++) {
                float2 f = __half22float2(vh[q]);
                accf[q * 2]     += we * f.x;
                accf[q * 2 + 1] += we * f.y;
            }
        }
    }
    float inv = 1.f / (z + 1e-16f);
    float4 o0 = make_float4(accf[0]*inv, accf[1]*inv, accf[2]*inv, accf[3]*inv);
    float4 o1 = make_float4(accf[4]*inv, accf[5]*inv, accf[6]*inv, accf[7]*inv);
    *reinterpret_cast<float4*>(out + (size_t)node * OUTF + lane * 8)     = o0;
    *reinterpret_cast<float4*>(out + (size_t)node * OUTF + lane * 8 + 4) = o1;
}

// ---------------- launch ----------------
extern "C" void kernel_launch(void* const* d_in, const int* in_sizes, int n_in,
                              void* d_out, int out_size) {
    const float* h     = nullptr;
    const int*   ei    = nullptr;
    const int*   src2  = nullptr;
    const int*   dst2  = nullptr;
    const float* W     = nullptr;
    const float* a_src = nullptr;
    const float* a_dst = nullptr;

    for (int i = 0; i < n_in; i++) {
        long sz = in_sizes[i];
        if (sz == 12800000L)      h = (const float*)d_in[i];
        else if (sz == 65536L)    W = (const float*)d_in[i];
        else if (sz == 256L) {
            if (!a_src) a_src = (const float*)d_in[i];
            else        a_dst = (const float*)d_in[i];
        }
        else if (sz == 1600000L)  ei = (const int*)d_in[i];
        else if (sz == 800000L) {
            if (!src2) src2 = (const int*)d_in[i];
            else       dst2 = (const int*)d_in[i];
        }
    }
    if (!h)                       h     = (const float*)d_in[0];
    if (!ei && !src2 && n_in > 1) ei    = (const int*)d_in[1];
    if (!W && n_in > 2)           W     = (const float*)d_in[2];
    if (!a_src && n_in > 3)       a_src = (const float*)d_in[3];
    if (!a_dst && n_in > 4)       a_dst = (const float*)d_in[4];

    const int* ebase = ei ? ei : src2;
    const int* dsep  = ei ? nullptr : dst2;
    float* out = (float*)d_out;

    cudaStream_t s2 = 0;
    cudaEvent_t ev_fork = nullptr, ev_join = nullptr;
    bool forked = (cudaStreamCreateWithFlags(&s2, cudaStreamNonBlocking) == cudaSuccess) &&
                  (cudaEventCreateWithFlags(&ev_fork, cudaEventDisableTiming) == cudaSuccess) &&
                  (cudaEventCreateWithFlags(&ev_join, cudaEventDisableTiming) == cudaSuccess);

    if (forked) {
        cudaEventRecord(ev_fork, 0);
        cudaStreamWaitEvent(s2, ev_fork, 0);
    }
    cudaStream_t sb = forked ? s2 : 0;

    // Side stream: detect + full CSR chain (only this chain consumes g_stride)
    detect_kernel<<<1, 32, 0, sb>>>(ebase);
    zero_deg_kernel<<<(NN + 255) / 256, 256, 0, sb>>>();
    count_deg_kernel<<<(EE + 255) / 256, 256, 0, sb>>>(ebase, dsep);
    scan_part1_kernel<<<SCAN_NB, 1024, 0, sb>>>();
    scan_part2_kernel<<<1, 64, 0, sb>>>();
    scan_part3_kernel<<<(NN + 255) / 256, 256, 0, sb>>>();
    scatter_kernel<<<(EE + 255) / 256, 256, 0, sb>>>(ebase, dsep);

    // Main stream: GEMM chain starts immediately
    dim3 tblock(32, 8);
    transpose_w_kernel<<<dim3(8, 8), tblock>>>(W);
    dim3 ggrid(OUTF / GBN, (NN + GBM - 1) / GBM);
    tf32_gemm_kernel<<<ggrid, 256>>>(h, NN);
    node_dots_kernel<<<(NN * 32 + 255) / 256, 256>>>(a_src, a_dst);

    if (forked) {
        cudaEventRecord(ev_join, s2);
        cudaStreamWaitEvent(0, ev_join, 0);
    }

    dim3 ablock(32, 8);
    aggregate_fused_kernel<<<(NN + 7) / 8, ablock>>>(out);
}

// round 14
// speedup vs baseline: 1.2846x; 1.0631x over previous
#include <cuda_runtime.h>
#include <cuda_fp16.h>
#include <cstdint>

// ---------------- Problem constants ----------------
#define NN 50000
#define EE 800000
#define KIN 256
#define HD 4
#define DD 64
#define OUTF (HD*DD)   // 256
#define SCAN_NB ((NN + 1023) / 1024)   // 49

// ---------------- Scratch (device globals; referenced ONLY from device code) ----------------
__device__ float  g_hp[(size_t)NN * OUTF];     // fp32 projected features (node_dots)
__device__ __half g_hph[(size_t)NN * OUTF];    // fp16 copy (aggregation gather)
__device__ __half g_wth[KIN * OUTF];           // W^T in fp16 [n][k]
__device__ float4 g_ssrc[NN];
__device__ float4 g_sdst[NN];
__device__ int    g_deg[NN];
__device__ int    g_off[NN];
__device__ int    g_cursor[NN];
__device__ int    g_csr[EE];
__device__ int    g_bsum[SCAN_NB];
__device__ int    g_boff[SCAN_NB];
__device__ int    g_stride;

__device__ __forceinline__ uint32_t h2_as_u32(__half2 h) {
    return *reinterpret_cast<uint32_t*>(&h);
}

// ---------------- detect int64 vs int32 edge_index (warp-parallel) ----------------
__global__ void detect_kernel(const int* __restrict__ ei) {
    int lane = threadIdx.x & 31;
    int odd_nz = 0, even_nz = 0;
    for (int i = lane; i < 512; i += 32) {
        if (ei[2 * i + 1] != 0) odd_nz++;
        if (ei[2 * i] != 0)     even_nz++;
    }
    unsigned ob = __ballot_sync(0xffffffffu, odd_nz > 0);
    unsigned eb = __ballot_sync(0xffffffffu, even_nz > 0);
    if (lane == 0) g_stride = (ob == 0u && eb != 0u) ? 2 : 1;
}

// ---------------- zero degree ----------------
__global__ void zero_deg_kernel() {
    int i = blockIdx.x * blockDim.x + threadIdx.x;
    if (i < NN) g_deg[i] = 0;
}

// ---------------- transpose W -> fp16: g_wth[n][k] = half(W[k][n]) ----------------
__global__ void transpose_w_kernel(const float* __restrict__ W) {
    __shared__ float tile[32][33];
    int bx = blockIdx.x * 32, by = blockIdx.y * 32;
    int tx = threadIdx.x, ty = threadIdx.y;
    #pragma unroll
    for (int r = 0; r < 4; r++)
        tile[ty + r * 8][tx] = W[(size_t)(by + ty + r * 8) * OUTF + bx + tx];
    __syncthreads();
    #pragma unroll
    for (int r = 0; r < 4; r++)
        g_wth[(size_t)(bx + ty + r * 8) * KIN + by + tx] = __float2half(tile[tx][ty + r * 8]);
}

// ---------------- fp16 tensor-core GEMM: g_hp[M,256] = A[M,256] @ W ----------------
// m16n8k16, fp32 accum. Smem stride 20 words/row (16 used + 4 pad):
// bank(g4*20 + l4) distinct for all 8 g4 groups -> conflict-free fragment loads.
#define GBM 128
#define GBN 128
#define GBK 32
#define LDW 20   // words (uint32) per row

__device__ __forceinline__ void mma_f16(float4& d,
                                        uint32_t a0, uint32_t a1, uint32_t a2, uint32_t a3,
                                        uint32_t b0, uint32_t b1) {
    asm volatile(
        "mma.sync.aligned.m16n8k16.row.col.f32.f16.f16.f32 "
        "{%0,%1,%2,%3}, {%4,%5,%6,%7}, {%8,%9}, {%0,%1,%2,%3};"
        : "+f"(d.x), "+f"(d.y), "+f"(d.z), "+f"(d.w)
        : "r"(a0), "r"(a1), "r"(a2), "r"(a3), "r"(b0), "r"(b1));
}

__global__ __launch_bounds__(256, 2)
void f16_gemm_kernel(const float* __restrict__ A, int M) {
    __shared__ uint32_t As[GBM * LDW];
    __shared__ uint32_t Bs[GBN * LDW];
    int tid  = threadIdx.x;
    int warp = tid >> 5, lane = tid & 31;
    int wm = warp & 1, wn = warp >> 1;          // 2x4 warps; warp tile 64x32
    int rowBase = blockIdx.y * GBM;
    int colBase = blockIdx.x * GBN;

    float4 acc[4][4];
    #pragma unroll
    for (int i = 0; i < 4; i++)
        #pragma unroll
        for (int j = 0; j < 4; j++) acc[i][j] = make_float4(0.f, 0.f, 0.f, 0.f);

    int la_row = tid >> 3;          // 0..31
    int la_col = (tid & 7) * 4;     // k offset in elements: 0,4,..,28

    float4 pa[4];
    uint2  pb[4];
    #pragma unroll
    for (int r = 0; r < 4; r++) {
        int gr = rowBase + la_row + r * 32;
        pa[r] = (gr < M) ? *reinterpret_cast<const float4*>(A + (size_t)gr * KIN + la_col)
                         : make_float4(0.f, 0.f, 0.f, 0.f);
        int gn = colBase + la_row + r * 32;     // < 256 always
        pb[r] = *reinterpret_cast<const uint2*>(g_wth + (size_t)gn * KIN + la_col);
    }

    int g4 = lane >> 2, l4 = lane & 3;
    for (int k0 = 0; k0 < KIN; k0 += GBK) {
        #pragma unroll
        for (int r = 0; r < 4; r++) {
            int row = la_row + r * 32;
            uint2 av;
            av.x = h2_as_u32(__floats2half2_rn(pa[r].x, pa[r].y));
            av.y = h2_as_u32(__floats2half2_rn(pa[r].z, pa[r].w));
            *reinterpret_cast<uint2*>(&As[row * LDW + (la_col >> 1)]) = av;
            *reinterpret_cast<uint2*>(&Bs[row * LDW + (la_col >> 1)]) = pb[r];
        }
        __syncthreads();
        if (k0 + GBK < KIN) {
            #pragma unroll
            for (int r = 0; r < 4; r++) {
                int gr = rowBase + la_row + r * 32;
                pa[r] = (gr < M) ? *reinterpret_cast<const float4*>(A + (size_t)gr * KIN + k0 + GBK + la_col)
                                 : make_float4(0.f, 0.f, 0.f, 0.f);
                int gn = colBase + la_row + r * 32;
                pb[r] = *reinterpret_cast<const uint2*>(g_wth + (size_t)gn * KIN + k0 + GBK + la_col);
            }
        }
        #pragma unroll
        for (int ks = 0; ks < 2; ks++) {        // two K=16 steps per 32-K block
            int kbw = ks * 8;                   // word offset
            uint32_t af[4][4], bf[4][2];
            #pragma unroll
            for (int mt = 0; mt < 4; mt++) {
                int r0 = wm * 64 + mt * 16 + g4;
                af[mt][0] = As[ r0      * LDW + kbw + l4    ];
                af[mt][1] = As[(r0 + 8) * LDW + kbw + l4    ];
                af[mt][2] = As[ r0      * LDW + kbw + l4 + 4];
                af[mt][3] = As[(r0 + 8) * LDW + kbw + l4 + 4];
            }
            #pragma unroll
            for (int nt = 0; nt < 4; nt++) {
                int n0 = wn * 32 + nt * 8 + g4;
                bf[nt][0] = Bs[n0 * LDW + kbw + l4    ];
                bf[nt][1] = Bs[n0 * LDW + kbw + l4 + 4];
            }
            #pragma unroll
            for (int mt = 0; mt < 4; mt++)
                #pragma unroll
                for (int nt = 0; nt < 4; nt++)
                    mma_f16(acc[mt][nt], af[mt][0], af[mt][1], af[mt][2], af[mt][3],
                            bf[nt][0], bf[nt][1]);
        }
        __syncthreads();
    }

    #pragma unroll
    for (int mt = 0; mt < 4; mt++) {
        int r = rowBase + wm * 64 + mt * 16 + g4;
        #pragma unroll
        for (int nt = 0; nt < 4; nt++) {
            int c = colBase + wn * 32 + nt * 8 + l4 * 2;
            if (r < M) {
                *reinterpret_cast<float2*>(g_hp + (size_t)r * OUTF + c) =
                    make_float2(acc[mt][nt].x, acc[mt][nt].y);
                *reinterpret_cast<__half2*>(g_hph + (size_t)r * OUTF + c) =
                    __floats2half2_rn(acc[mt][nt].x, acc[mt][nt].y);
            }
            if (r + 8 < M) {
                *reinterpret_cast<float2*>(g_hp + (size_t)(r + 8) * OUTF + c) =
                    make_float2(acc[mt][nt].z, acc[mt][nt].w);
                *reinterpret_cast<__half2*>(g_hph + (size_t)(r + 8) * OUTF + c) =
                    __floats2half2_rn(acc[mt][nt].z, acc[mt][nt].w);
            }
        }
    }
}

// ---------------- per-node logits ----------------
__global__ void node_dots_kernel(const float* __restrict__ a_src,
                                 const float* __restrict__ a_dst) {
    int warp = (blockIdx.x * blockDim.x + threadIdx.x) >> 5;
    int lane = threadIdx.x & 31;
    if (warp >= NN) return;
    const float4* row = reinterpret_cast<const float4*>(g_hp + (size_t)warp * OUTF);
    const float4* as4 = reinterpret_cast<const float4*>(a_src);
    const float4* ad4 = reinterpret_cast<const float4*>(a_dst);
    float4 r0 = row[lane * 2], r1 = row[lane * 2 + 1];
    float4 a0 = as4[lane * 2], a1 = as4[lane * 2 + 1];
    float4 d0 = ad4[lane * 2], d1 = ad4[lane * 2 + 1];
    float ps = r0.x*a0.x + r0.y*a0.y + r0.z*a0.z + r0.w*a0.w
             + r1.x*a1.x + r1.y*a1.y + r1.z*a1.z + r1.w*a1.w;
    float pd = r0.x*d0.x + r0.y*d0.y + r0.z*d0.z + r0.w*d0.w
             + r1.x*d1.x + r1.y*d1.y + r1.z*d1.z + r1.w*d1.w;
    #pragma unroll
    for (int o = 4; o; o >>= 1) {
        ps += __shfl_xor_sync(0xffffffffu, ps, o);
        pd += __shfl_xor_sync(0xffffffffu, pd, o);
    }
    float s0 = __shfl_sync(0xffffffffu, ps, 0),  s1 = __shfl_sync(0xffffffffu, ps, 8);
    float s2 = __shfl_sync(0xffffffffu, ps, 16), s3 = __shfl_sync(0xffffffffu, ps, 24);
    float d0s = __shfl_sync(0xffffffffu, pd, 0),  d1s = __shfl_sync(0xffffffffu, pd, 8);
    float d2s = __shfl_sync(0xffffffffu, pd, 16), d3s = __shfl_sync(0xffffffffu, pd, 24);
    if (lane == 0) {
        g_ssrc[warp] = make_float4(s0, s1, s2, s3);
        g_sdst[warp] = make_float4(d0s, d1s, d2s, d3s);
    }
}

// ---------------- count in-degree ----------------
__global__ void count_deg_kernel(const int* __restrict__ ei, const int* __restrict__ dst_sep) {
    int e = blockIdx.x * blockDim.x + threadIdx.x;
    if (e >= EE) return;
    int st = g_stride;
    const int* d_base = dst_sep ? dst_sep : ei + (size_t)EE * st;
    int u = d_base[(size_t)e * st];
    if (u >= 0 && u < NN) atomicAdd(&g_deg[u], 1);
}

// ---------------- multi-block exclusive scan ----------------
__global__ void scan_part1_kernel() {
    __shared__ int warpsums[32];
    int t = threadIdx.x, lane = t & 31, wid = t >> 5;
    int idx = blockIdx.x * 1024 + t;
    int v = (idx < NN) ? g_deg[idx] : 0;
    int x = v;
    #pragma unroll
    for (int o = 1; o < 32; o <<= 1) {
        int y = __shfl_up_sync(0xffffffffu, x, o);
        if (lane >= o) x += y;
    }
    if (lane == 31) warpsums[wid] = x;
    __syncthreads();
    if (wid == 0) {
        int s = warpsums[lane];
        #pragma unroll
        for (int o = 1; o < 32; o <<= 1) {
            int y = __shfl_up_sync(0xffffffffu, s, o);
            if (lane >= o) s += y;
        }
        warpsums[lane] = s;
    }
    __syncthreads();
    int incl = x + (wid > 0 ? warpsums[wid - 1] : 0);
    if (idx < NN) g_off[idx] = incl - v;
    if (t == 1023) g_bsum[blockIdx.x] = incl;
}

__global__ void scan_part2_kernel() {
    __shared__ int ws[2];
    int t = threadIdx.x, lane = t & 31, wid = t >> 5;
    int v = (t < SCAN_NB) ? g_bsum[t] : 0;
    int x = v;
    #pragma unroll
    for (int o = 1; o < 32; o <<= 1) {
        int y = __shfl_up_sync(0xffffffffu, x, o);
        if (lane >= o) x += y;
    }
    if (lane == 31) ws[wid] = x;
    __syncthreads();
    int excl = x - v + (wid > 0 ? ws[0] : 0);
    if (t < SCAN_NB) g_boff[t] = excl;
}

__global__ void scan_part3_kernel() {
    int idx = blockIdx.x * blockDim.x + threadIdx.x;
    if (idx < NN) {
        int o = g_off[idx] + g_boff[idx >> 10];
        g_off[idx] = o;
        g_cursor[idx] = o;
    }
}

// ---------------- pure CSR scatter ----------------
__global__ void scatter_kernel(const int* __restrict__ ei, const int* __restrict__ dst_sep) {
    int e = blockIdx.x * blockDim.x + threadIdx.x;
    if (e >= EE) return;
    int st = g_stride;
    const int* d_base = dst_sep ? dst_sep : ei + (size_t)EE * st;
    int ud = d_base[(size_t)e * st];
    if (ud < 0 || ud >= NN) return;
    int us = ei[(size_t)e * st];
    if (us < 0) us = 0;
    if (us >= NN) us = NN - 1;
    int p = atomicAdd(&g_cursor[ud], 1);
    if (p >= 0 && p < EE) g_csr[p] = us;
}

// ---------------- fused softmax + aggregation: batched-load full tiles ----------------
__global__ __launch_bounds__(256)
void aggregate_fused_kernel(float* __restrict__ out) {
    int lane = threadIdx.x;
    int yn = threadIdx.y;
    int node = blockIdx.x * 8 + yn;
    if (node >= NN) return;
    int start = g_off[node], dn = g_deg[node];
    int hq = lane >> 3;
    int pe = lane & 7;
    float sdv = (&g_sdst[node].x)[hq];

    float accf[8] = {0.f,0.f,0.f,0.f,0.f,0.f,0.f,0.f};
    float z = 0.f;

    int full = dn & ~7;
    for (int base = 0; base < full; base += 8) {
        int s = g_csr[start + base + pe];
        float x = (&g_ssrc[s].x)[hq] + sdv;
        x = fmaxf(x, 0.2f * x);
        float w = __expf(x);

        int   se[8];
        float we[8];
        #pragma unroll
        for (int e = 0; e < 8; e++) {
            se[e] = __shfl_sync(0xffffffffu, s, e);
            we[e] = __shfl_sync(0xffffffffu, w, (hq << 3) | e);
        }
        uint4 vu[8];
        #pragma unroll
        for (int e = 0; e < 8; e++)
            vu[e] = *reinterpret_cast<const uint4*>(g_hph + (size_t)se[e] * OUTF + lane * 8);
        #pragma unroll
        for (int e = 0; e < 8; e++) {
            const __half2* vh = reinterpret_cast<const __half2*>(&vu[e]);
            z += we[e];
            #pragma unroll
            for (int q = 0; q < 4; q++) {
                float2 f = __half22float2(vh[q]);
                accf[q * 2]     += we[e] * f.x;
                accf[q * 2 + 1] += we[e] * f.y;
            }
        }
    }
    int cnt = dn - full;
    if (cnt > 0) {
        float w = 0.f; int s = 0;
        if (pe < cnt) {
            s = g_csr[start + full + pe];
            float x = (&g_ssrc[s].x)[hq] + sdv;
            x = fmaxf(x, 0.2f * x);
            w = __expf(x);
        }
        for (int e = 0; e < cnt; e++) {
            int   se = __shfl_sync(0xffffffffu, s, e);
            float we = __shfl_sync(0xffffffffu, w, (hq << 3) | e);
            uint4 vu = *reinterpret_cast<const uint4*>(g_hph + (size_t)se * OUTF + lane * 8);
            const __half2* vh = reinterpret_cast<const __half2*>(&vu);
            z += we;
            #pragma unroll
            for (int q = 0; q < 4; q++) {
                float2 f = __half22float2(vh[q]);
                accf[q * 2]     += we * f.x;
                accf[q * 2 + 1] += we * f.y;
            }
        }
    }
    float inv = 1.f / (z + 1e-16f);
    float4 o0 = make_float4(accf[0]*inv, accf[1]*inv, accf[2]*inv, accf[3]*inv);
    float4 o1 = make_float4(accf[4]*inv, accf[5]*inv, accf[6]*inv, accf[7]*inv);
    *reinterpret_cast<float4*>(out + (size_t)node * OUTF + lane * 8)     = o0;
    *reinterpret_cast<float4*>(out + (size_t)node * OUTF + lane * 8 + 4) = o1;
}

// ---------------- launch ----------------
extern "C" void kernel_launch(void* const* d_in, const int* in_sizes, int n_in,
                              void* d_out, int out_size) {
    const float* h     = nullptr;
    const int*   ei    = nullptr;
    const int*   src2  = nullptr;
    const int*   dst2  = nullptr;
    const float* W     = nullptr;
    const float* a_src = nullptr;
    const float* a_dst = nullptr;

    for (int i = 0; i < n_in; i++) {
        long sz = in_sizes[i];
        if (sz == 12800000L)      h = (const float*)d_in[i];
        else if (sz == 65536L)    W = (const float*)d_in[i];
        else if (sz == 256L) {
            if (!a_src) a_src = (const float*)d_in[i];
            else        a_dst = (const float*)d_in[i];
        }
        else if (sz == 1600000L)  ei = (const int*)d_in[i];
        else if (sz == 800000L) {
            if (!src2) src2 = (const int*)d_in[i];
            else       dst2 = (const int*)d_in[i];
        }
    }
    if (!h)                       h     = (const float*)d_in[0];
    if (!ei && !src2 && n_in > 1) ei    = (const int*)d_in[1];
    if (!W && n_in > 2)           W     = (const float*)d_in[2];
    if (!a_src && n_in > 3)       a_src = (const float*)d_in[3];
    if (!a_dst && n_in > 4)       a_dst = (const float*)d_in[4];

    const int* ebase = ei ? ei : src2;
    const int* dsep  = ei ? nullptr : dst2;
    float* out = (float*)d_out;

    cudaStream_t s2 = 0;
    cudaEvent_t ev_fork = nullptr, ev_join = nullptr;
    bool forked = (cudaStreamCreateWithFlags(&s2, cudaStreamNonBlocking) == cudaSuccess) &&
                  (cudaEventCreateWithFlags(&ev_fork, cudaEventDisableTiming) == cudaSuccess) &&
                  (cudaEventCreateWithFlags(&ev_join, cudaEventDisableTiming) == cudaSuccess);

    if (forked) {
        cudaEventRecord(ev_fork, 0);
        cudaStreamWaitEvent(s2, ev_fork, 0);
    }
    cudaStream_t sb = forked ? s2 : 0;

    // Side stream: detect + full CSR chain
    detect_kernel<<<1, 32, 0, sb>>>(ebase);
    zero_deg_kernel<<<(NN + 255) / 256, 256, 0, sb>>>();
    count_deg_kernel<<<(EE + 255) / 256, 256, 0, sb>>>(ebase, dsep);
    scan_part1_kernel<<<SCAN_NB, 1024, 0, sb>>>();
    scan_part2_kernel<<<1, 64, 0, sb>>>();
    scan_part3_kernel<<<(NN + 255) / 256, 256, 0, sb>>>();
    scatter_kernel<<<(EE + 255) / 256, 256, 0, sb>>>(ebase, dsep);

    // Main stream: GEMM chain
    dim3 tblock(32, 8);
    transpose_w_kernel<<<dim3(8, 8), tblock>>>(W);
    dim3 ggrid(OUTF / GBN, (NN + GBM - 1) / GBM);
    f16_gemm_kernel<<<ggrid, 256>>>(h, NN);
    node_dots_kernel<<<(NN * 32 + 255) / 256, 256>>>(a_src, a_dst);

    if (forked) {
        cudaEventRecord(ev_join, s2);
        cudaStreamWaitEvent(0, ev_join, 0);
    }

    dim3 ablock(32, 8);
    aggregate_fused_kernel<<<(NN + 7) / 8, ablock>>>(out);
}

// round 15
// speedup vs baseline: 1.5068x; 1.1730x over previous
#include <cuda_runtime.h>
#include <cuda_fp16.h>
#include <cstdint>

// ---------------- Problem constants ----------------
#define NN 50000
#define EE 800000
#define KIN 256
#define HD 4
#define DD 64
#define OUTF (HD*DD)   // 256
#define SCAN_NB ((NN + 1023) / 1024)   // 49

// ---------------- Scratch (device globals; referenced ONLY from device code) ----------------
__device__ __half g_hph[(size_t)NN * OUTF];    // fp16 projected features (aggregation gather)
__device__ __half g_wth[KIN * OUTF];           // W^T in fp16 [n][k]
__device__ float4 g_ssrc[NN];                  // per-node src logits (atomic-accumulated)
__device__ float4 g_sdst[NN];                  // per-node dst logits
__device__ int    g_deg[NN];
__device__ int    g_off[NN];
__device__ int    g_cursor[NN];
__device__ int    g_csr[EE];
__device__ int    g_bsum[SCAN_NB];
__device__ int    g_boff[SCAN_NB];
__device__ int    g_stride;

__device__ __forceinline__ uint32_t h2_as_u32(__half2 h) {
    return *reinterpret_cast<uint32_t*>(&h);
}

// ---------------- detect int64 vs int32 edge_index (warp-parallel) ----------------
__global__ void detect_kernel(const int* __restrict__ ei) {
    int lane = threadIdx.x & 31;
    int odd_nz = 0, even_nz = 0;
    for (int i = lane; i < 512; i += 32) {
        if (ei[2 * i + 1] != 0) odd_nz++;
        if (ei[2 * i] != 0)     even_nz++;
    }
    unsigned ob = __ballot_sync(0xffffffffu, odd_nz > 0);
    unsigned eb = __ballot_sync(0xffffffffu, even_nz > 0);
    if (lane == 0) g_stride = (ob == 0u && eb != 0u) ? 2 : 1;
}

// ---------------- zero degree ----------------
__global__ void zero_deg_kernel() {
    int i = blockIdx.x * blockDim.x + threadIdx.x;
    if (i < NN) g_deg[i] = 0;
}

// ---------------- zero logits (main stream, before GEMM) ----------------
__global__ void zero_s_kernel() {
    int i = blockIdx.x * blockDim.x + threadIdx.x;
    if (i < NN * HD) {
        reinterpret_cast<float*>(g_ssrc)[i] = 0.f;
        reinterpret_cast<float*>(g_sdst)[i] = 0.f;
    }
}

// ---------------- transpose W -> fp16: g_wth[n][k] = half(W[k][n]) ----------------
__global__ void transpose_w_kernel(const float* __restrict__ W) {
    __shared__ float tile[32][33];
    int bx = blockIdx.x * 32, by = blockIdx.y * 32;
    int tx = threadIdx.x, ty = threadIdx.y;
    #pragma unroll
    for (int r = 0; r < 4; r++)
        tile[ty + r * 8][tx] = W[(size_t)(by + ty + r * 8) * OUTF + bx + tx];
    __syncthreads();
    #pragma unroll
    for (int r = 0; r < 4; r++)
        g_wth[(size_t)(bx + ty + r * 8) * KIN + by + tx] = __float2half(tile[tx][ty + r * 8]);
}

// ---------------- fp16 GEMM + fused attention-dot epilogue ----------------
#define GBM 128
#define GBN 128
#define GBK 32
#define LDW 20   // words per row (16 used + 4 pad); conflict-free fragment loads

__device__ __forceinline__ void mma_f16(float4& d,
                                        uint32_t a0, uint32_t a1, uint32_t a2, uint32_t a3,
                                        uint32_t b0, uint32_t b1) {
    asm volatile(
        "mma.sync.aligned.m16n8k16.row.col.f32.f16.f16.f32 "
        "{%0,%1,%2,%3}, {%4,%5,%6,%7}, {%8,%9}, {%0,%1,%2,%3};"
        : "+f"(d.x), "+f"(d.y), "+f"(d.z), "+f"(d.w)
        : "r"(a0), "r"(a1), "r"(a2), "r"(a3), "r"(b0), "r"(b1));
}

__global__ __launch_bounds__(256, 2)
void f16_gemm_kernel(const float* __restrict__ A,
                     const float* __restrict__ a_src,
                     const float* __restrict__ a_dst, int M) {
    __shared__ uint32_t As[GBM * LDW];
    __shared__ uint32_t Bs[GBN * LDW];
    int tid  = threadIdx.x;
    int warp = tid >> 5, lane = tid & 31;
    int wm = warp & 1, wn = warp >> 1;          // 2x4 warps; warp tile 64x32
    int rowBase = blockIdx.y * GBM;
    int colBase = blockIdx.x * GBN;

    float4 acc[4][4];
    #pragma unroll
    for (int i = 0; i < 4; i++)
        #pragma unroll
        for (int j = 0; j < 4; j++) acc[i][j] = make_float4(0.f, 0.f, 0.f, 0.f);

    int la_row = tid >> 3;
    int la_col = (tid & 7) * 4;

    float4 pa[4];
    uint2  pb[4];
    #pragma unroll
    for (int r = 0; r < 4; r++) {
        int gr = rowBase + la_row + r * 32;
        pa[r] = (gr < M) ? *reinterpret_cast<const float4*>(A + (size_t)gr * KIN + la_col)
                         : make_float4(0.f, 0.f, 0.f, 0.f);
        int gn = colBase + la_row + r * 32;
        pb[r] = *reinterpret_cast<const uint2*>(g_wth + (size_t)gn * KIN + la_col);
    }

    int g4 = lane >> 2, l4 = lane & 3;
    for (int k0 = 0; k0 < KIN; k0 += GBK) {
        #pragma unroll
        for (int r = 0; r < 4; r++) {
            int row = la_row + r * 32;
            uint2 av;
            av.x = h2_as_u32(__floats2half2_rn(pa[r].x, pa[r].y));
            av.y = h2_as_u32(__floats2half2_rn(pa[r].z, pa[r].w));
            *reinterpret_cast<uint2*>(&As[row * LDW + (la_col >> 1)]) = av;
            *reinterpret_cast<uint2*>(&Bs[row * LDW + (la_col >> 1)]) = pb[r];
        }
        __syncthreads();
        if (k0 + GBK < KIN) {
            #pragma unroll
            for (int r = 0; r < 4; r++) {
                int gr = rowBase + la_row + r * 32;
                pa[r] = (gr < M) ? *reinterpret_cast<const float4*>(A + (size_t)gr * KIN + k0 + GBK + la_col)
                                 : make_float4(0.f, 0.f, 0.f, 0.f);
                int gn = colBase + la_row + r * 32;
                pb[r] = *reinterpret_cast<const uint2*>(g_wth + (size_t)gn * KIN + k0 + GBK + la_col);
            }
        }
        #pragma unroll
        for (int ks = 0; ks < 2; ks++) {
            int kbw = ks * 8;
            uint32_t af[4][4], bf[4][2];
            #pragma unroll
            for (int mt = 0; mt < 4; mt++) {
                int r0 = wm * 64 + mt * 16 + g4;
                af[mt][0] = As[ r0      * LDW + kbw + l4    ];
                af[mt][1] = As[(r0 + 8) * LDW + kbw + l4    ];
                af[mt][2] = As[ r0      * LDW + kbw + l4 + 4];
                af[mt][3] = As[(r0 + 8) * LDW + kbw + l4 + 4];
            }
            #pragma unroll
            for (int nt = 0; nt < 4; nt++) {
                int n0 = wn * 32 + nt * 8 + g4;
                bf[nt][0] = Bs[n0 * LDW + kbw + l4    ];
                bf[nt][1] = Bs[n0 * LDW + kbw + l4 + 4];
            }
            #pragma unroll
            for (int mt = 0; mt < 4; mt++)
                #pragma unroll
                for (int nt = 0; nt < 4; nt++)
                    mma_f16(acc[mt][nt], af[mt][0], af[mt][1], af[mt][2], af[mt][3],
                            bf[nt][0], bf[nt][1]);
        }
        __syncthreads();
    }

    // ---- epilogue: fp16 store + fused attention dot partials ----
    // This warp's 32 columns lie in exactly one head.
    int warpCol = colBase + wn * 32;
    int head = warpCol >> 6;
    // per-thread a_src/a_dst values for its 8 columns
    float asv[8], adv[8];
    #pragma unroll
    for (int nt = 0; nt < 4; nt++) {
        int c = warpCol + nt * 8 + l4 * 2;
        asv[nt * 2]     = a_src[c];     asv[nt * 2 + 1] = a_src[c + 1];
        adv[nt * 2]     = a_dst[c];     adv[nt * 2 + 1] = a_dst[c + 1];
    }
    #pragma unroll
    for (int mt = 0; mt < 4; mt++) {
        int r = rowBase + wm * 64 + mt * 16 + g4;
        float psl = 0.f, pdl = 0.f;     // row r partials
        float psh = 0.f, pdh = 0.f;     // row r+8 partials
        #pragma unroll
        for (int nt = 0; nt < 4; nt++) {
            int c = warpCol + nt * 8 + l4 * 2;
            if (r < M)
                *reinterpret_cast<__half2*>(g_hph + (size_t)r * OUTF + c) =
                    __floats2half2_rn(acc[mt][nt].x, acc[mt][nt].y);
            if (r + 8 < M)
                *reinterpret_cast<__half2*>(g_hph + (size_t)(r + 8) * OUTF + c) =
                    __floats2half2_rn(acc[mt][nt].z, acc[mt][nt].w);
            psl += acc[mt][nt].x * asv[nt * 2] + acc[mt][nt].y * asv[nt * 2 + 1];
            pdl += acc[mt][nt].x * adv[nt * 2] + acc[mt][nt].y * adv[nt * 2 + 1];
            psh += acc[mt][nt].z * asv[nt * 2] + acc[mt][nt].w * asv[nt * 2 + 1];
            pdh += acc[mt][nt].z * adv[nt * 2] + acc[mt][nt].w * adv[nt * 2 + 1];
        }
        // reduce across the 4 lanes sharing this row (l4 = 0..3)
        #pragma unroll
        for (int o = 1; o < 4; o <<= 1) {
            psl += __shfl_xor_sync(0xffffffffu, psl, o);
            pdl += __shfl_xor_sync(0xffffffffu, pdl, o);
            psh += __shfl_xor_sync(0xffffffffu, psh, o);
            pdh += __shfl_xor_sync(0xffffffffu, pdh, o);
        }
        if (l4 == 0) {
            if (r < M) {
                atomicAdd(reinterpret_cast<float*>(g_ssrc) + (size_t)r * HD + head, psl);
                atomicAdd(reinterpret_cast<float*>(g_sdst) + (size_t)r * HD + head, pdl);
            }
            if (r + 8 < M) {
                atomicAdd(reinterpret_cast<float*>(g_ssrc) + (size_t)(r + 8) * HD + head, psh);
                atomicAdd(reinterpret_cast<float*>(g_sdst) + (size_t)(r + 8) * HD + head, pdh);
            }
        }
    }
}

// ---------------- count in-degree ----------------
__global__ void count_deg_kernel(const int* __restrict__ ei, const int* __restrict__ dst_sep) {
    int e = blockIdx.x * blockDim.x + threadIdx.x;
    if (e >= EE) return;
    int st = g_stride;
    const int* d_base = dst_sep ? dst_sep : ei + (size_t)EE * st;
    int u = d_base[(size_t)e * st];
    if (u >= 0 && u < NN) atomicAdd(&g_deg[u], 1);
}

// ---------------- multi-block exclusive scan ----------------
__global__ void scan_part1_kernel() {
    __shared__ int warpsums[32];
    int t = threadIdx.x, lane = t & 31, wid = t >> 5;
    int idx = blockIdx.x * 1024 + t;
    int v = (idx < NN) ? g_deg[idx] : 0;
    int x = v;
    #pragma unroll
    for (int o = 1; o < 32; o <<= 1) {
        int y = __shfl_up_sync(0xffffffffu, x, o);
        if (lane >= o) x += y;
    }
    if (lane == 31) warpsums[wid] = x;
    __syncthreads();
    if (wid == 0) {
        int s = warpsums[lane];
        #pragma unroll
        for (int o = 1; o < 32; o <<= 1) {
            int y = __shfl_up_sync(0xffffffffu, s, o);
            if (lane >= o) s += y;
        }
        warpsums[lane] = s;
    }
    __syncthreads();
    int incl = x + (wid > 0 ? warpsums[wid - 1] : 0);
    if (idx < NN) g_off[idx] = incl - v;
    if (t == 1023) g_bsum[blockIdx.x] = incl;
}

__global__ void scan_part2_kernel() {
    __shared__ int ws[2];
    int t = threadIdx.x, lane = t & 31, wid = t >> 5;
    int v = (t < SCAN_NB) ? g_bsum[t] : 0;
    int x = v;
    #pragma unroll
    for (int o = 1; o < 32; o <<= 1) {
        int y = __shfl_up_sync(0xffffffffu, x, o);
        if (lane >= o) x += y;
    }
    if (lane == 31) ws[wid] = x;
    __syncthreads();
    int excl = x - v + (wid > 0 ? ws[0] : 0);
    if (t < SCAN_NB) g_boff[t] = excl;
}

__global__ void scan_part3_kernel() {
    int idx = blockIdx.x * blockDim.x + threadIdx.x;
    if (idx < NN) {
        int o = g_off[idx] + g_boff[idx >> 10];
        g_off[idx] = o;
        g_cursor[idx] = o;
    }
}

// ---------------- pure CSR scatter ----------------
__global__ void scatter_kernel(const int* __restrict__ ei, const int* __restrict__ dst_sep) {
    int e = blockIdx.x * blockDim.x + threadIdx.x;
    if (e >= EE) return;
    int st = g_stride;
    const int* d_base = dst_sep ? dst_sep : ei + (size_t)EE * st;
    int ud = d_base[(size_t)e * st];
    if (ud < 0 || ud >= NN) return;
    int us = ei[(size_t)e * st];
    if (us < 0) us = 0;
    if (us >= NN) us = NN - 1;
    int p = atomicAdd(&g_cursor[ud], 1);
    if (p >= 0 && p < EE) g_csr[p] = us;
}

// ---------------- fused softmax + aggregation: batched-load full tiles ----------------
__global__ __launch_bounds__(256)
void aggregate_fused_kernel(float* __restrict__ out) {
    int lane = threadIdx.x;
    int yn = threadIdx.y;
    int node = blockIdx.x * 8 + yn;
    if (node >= NN) return;
    int start = g_off[node], dn = g_deg[node];
    int hq = lane >> 3;
    int pe = lane & 7;
    float sdv = (&g_sdst[node].x)[hq];

    float accf[8] = {0.f,0.f,0.f,0.f,0.f,0.f,0.f,0.f};
    float z = 0.f;

    int full = dn & ~7;
    for (int base = 0; base < full; base += 8) {
        int s = g_csr[start + base + pe];
        float x = (&g_ssrc[s].x)[hq] + sdv;
        x = fmaxf(x, 0.2f * x);
        float w = __expf(x);

        int   se[8];
        float we[8];
        #pragma unroll
        for (int e = 0; e < 8; e++) {
            se[e] = __shfl_sync(0xffffffffu, s, e);
            we[e] = __shfl_sync(0xffffffffu, w, (hq << 3) | e);
        }
        uint4 vu[8];
        #pragma unroll
        for (int e = 0; e < 8; e++)
            vu[e] = *reinterpret_cast<const uint4*>(g_hph + (size_t)se[e] * OUTF + lane * 8);
        #pragma unroll
        for (int e = 0; e < 8; e++) {
            const __half2* vh = reinterpret_cast<const __half2*>(&vu[e]);
            z += we[e];
            #pragma unroll
            for (int q = 0; q < 4; q++) {
                float2 f = __half22float2(vh[q]);
                accf[q * 2]     += we[e] * f.x;
                accf[q * 2 + 1] += we[e] * f.y;
            }
        }
    }
    int cnt = dn - full;
    if (cnt > 0) {
        float w = 0.f; int s = 0;
        if (pe < cnt) {
            s = g_csr[start + full + pe];
            float x = (&g_ssrc[s].x)[hq] + sdv;
            x = fmaxf(x, 0.2f * x);
            w = __expf(x);
        }
        for (int e = 0; e < cnt; e++) {
            int   se = __shfl_sync(0xffffffffu, s, e);
            float we = __shfl_sync(0xffffffffu, w, (hq << 3) | e);
            uint4 vu = *reinterpret_cast<const uint4*>(g_hph + (size_t)se * OUTF + lane * 8);
            const __half2* vh = reinterpret_cast<const __half2*>(&vu);
            z += we;
            #pragma unroll
            for (int q = 0; q < 4; q++) {
                float2 f = __half22float2(vh[q]);
                accf[q * 2]     += we * f.x;
                accf[q * 2 + 1] += we * f.y;
            }
        }
    }
    float inv = 1.f / (z + 1e-16f);
    float4 o0 = make_float4(accf[0]*inv, accf[1]*inv, accf[2]*inv, accf[3]*inv);
    float4 o1 = make_float4(accf[4]*inv, accf[5]*inv, accf[6]*inv, accf[7]*inv);
    *reinterpret_cast<float4*>(out + (size_t)node * OUTF + lane * 8)     = o0;
    *reinterpret_cast<float4*>(out + (size_t)node * OUTF + lane * 8 + 4) = o1;
}

// ---------------- launch ----------------
extern "C" void kernel_launch(void* const* d_in, const int* in_sizes, int n_in,
                              void* d_out, int out_size) {
    const float* h     = nullptr;
    const int*   ei    = nullptr;
    const int*   src2  = nullptr;
    const int*   dst2  = nullptr;
    const float* W     = nullptr;
    const float* a_src = nullptr;
    const float* a_dst = nullptr;

    for (int i = 0; i < n_in; i++) {
        long sz = in_sizes[i];
        if (sz == 12800000L)      h = (const float*)d_in[i];
        else if (sz == 65536L)    W = (const float*)d_in[i];
        else if (sz == 256L) {
            if (!a_src) a_src = (const float*)d_in[i];
            else        a_dst = (const float*)d_in[i];
        }
        else if (sz == 1600000L)  ei = (const int*)d_in[i];
        else if (sz == 800000L) {
            if (!src2) src2 = (const int*)d_in[i];
            else       dst2 = (const int*)d_in[i];
        }
    }
    if (!h)                       h     = (const float*)d_in[0];
    if (!ei && !src2 && n_in > 1) ei    = (const int*)d_in[1];
    if (!W && n_in > 2)           W     = (const float*)d_in[2];
    if (!a_src && n_in > 3)       a_src = (const float*)d_in[3];
    if (!a_dst && n_in > 4)       a_dst = (const float*)d_in[4];

    const int* ebase = ei ? ei : src2;
    const int* dsep  = ei ? nullptr : dst2;
    float* out = (float*)d_out;

    cudaStream_t s2 = 0;
    cudaEvent_t ev_fork = nullptr, ev_join = nullptr;
    bool forked = (cudaStreamCreateWithFlags(&s2, cudaStreamNonBlocking) == cudaSuccess) &&
                  (cudaEventCreateWithFlags(&ev_fork, cudaEventDisableTiming) == cudaSuccess) &&
                  (cudaEventCreateWithFlags(&ev_join, cudaEventDisableTiming) == cudaSuccess);

    if (forked) {
        cudaEventRecord(ev_fork, 0);
        cudaStreamWaitEvent(s2, ev_fork, 0);
    }
    cudaStream_t sb = forked ? s2 : 0;

    // Side stream: detect + full CSR chain
    detect_kernel<<<1, 32, 0, sb>>>(ebase);
    zero_deg_kernel<<<(NN + 255) / 256, 256, 0, sb>>>();
    count_deg_kernel<<<(EE + 255) / 256, 256, 0, sb>>>(ebase, dsep);
    scan_part1_kernel<<<SCAN_NB, 1024, 0, sb>>>();
    scan_part2_kernel<<<1, 64, 0, sb>>>();
    scan_part3_kernel<<<(NN + 255) / 256, 256, 0, sb>>>();
    scatter_kernel<<<(EE + 255) / 256, 256, 0, sb>>>(ebase, dsep);

    // Main stream: zero logits, transpose, GEMM(+fused dots)
    zero_s_kernel<<<(NN * HD + 255) / 256, 256>>>();
    dim3 tblock(32, 8);
    transpose_w_kernel<<<dim3(8, 8), tblock>>>(W);
    dim3 ggrid(OUTF / GBN, (NN + GBM - 1) / GBM);
    f16_gemm_kernel<<<ggrid, 256>>>(h, a_src, a_dst, NN);

    if (forked) {
        cudaEventRecord(ev_join, s2);
        cudaStreamWaitEvent(0, ev_join, 0);
    }

    dim3 ablock(32, 8);
    aggregate_fused_kernel<<<(NN + 7) / 8, ablock>>>(out);
}